// round 12
// baseline (speedup 1.0000x reference)
#include <cuda_runtime.h>
#include <cstdint>

// Shapes: re, gt are (B=32, C=10, H=192, W=320) float32, contiguous.
#define NB     32
#define NC     10
#define HW4    15360                 // (192*320)/4 float4 groups per channel
#define N4     (NB*HW4)              // 491520 groups total
#define TILE   64                    // float4 groups per tile
#define TILES  (N4/TILE)             // 7680 tiles
#define CTAT   4                     // tiles per CTA
#define GRID   (TILES/CTAT)          // 1920 CTAs
#define BLK    256
#define TPI    (HW4/TILE)            // 240 tiles per image
#define NACC   6
#define EPSF   6e-8f

// [0]=nv [1]=num_pos [2]=focal_sum
// [3]=A (pos+height+const) [4]=B (len1+trig1) [5]=C (len2+trig2)
__device__ float g_part[NACC][GRID];
__device__ unsigned int g_count = 0;   // reset by last block each launch

__device__ __forceinline__ float sl1(float d) {
    float ad = fabsf(d);
    return ad < 1.0f ? 0.5f * d * d : ad - 0.5f;
}

__device__ __forceinline__ void cp16(uint32_t dst, const float4* src) {
    asm volatile("cp.async.cg.shared.global [%0], [%1], 16;"
                 :: "r"(dst), "l"(src));
}

__global__ void __launch_bounds__(BLK, 4)
loss_kernel(const float* __restrict__ re, const float* __restrict__ gt,
            float* __restrict__ out) {
    // Two 20 KB stages: stream s (0-9 = gt ch s, 10-19 = re ch s-10) x 64 groups.
    __shared__ float4 stage[2][20 * TILE];          // 40 KB

    const int tid = threadIdx.x;
    const float4* __restrict__ gt4 = (const float4*)gt;
    const float4* __restrict__ re4 = (const float4*)re;
    const int t0 = blockIdx.x * CTAT;               // first tile of this CTA

    auto prefetch = [&](int T, int stg) {
        const int b   = T / TPI;
        const int off = (T - b * TPI) * TILE;
        const float4* gbase = gt4 + (size_t)b * (NC * HW4) + off;
        const float4* rbase = re4 + (size_t)b * (NC * HW4) + off;
        const uint32_t sbase =
            (uint32_t)__cvta_generic_to_shared(&stage[stg][0]);
#pragma unroll
        for (int k = 0; k < (20 * TILE) / BLK; k++) {   // 5 cp.async / thread
            const int idx = k * BLK + tid;              // 0..1279
            const int s   = idx >> 6;                   // stream 0..19
            const int g   = idx & 63;                   // group in tile
            const float4* src = (s < 10) ? (gbase + s * HW4 + g)
                                         : (rbase + (s - 10) * HW4 + g);
            cp16(sbase + (uint32_t)idx * 16u, src);
        }
        asm volatile("cp.async.commit_group;");
    };

    float a_nv = 0.f, a_np = 0.f, a_f = 0.f, a_A = 0.f, a_B = 0.f, a_C = 0.f;

    prefetch(t0, 0);
    for (int t = 0; t < CTAT; t++) {
        if (t + 1 < CTAT) {
            prefetch(t0 + t + 1, (t + 1) & 1);
            asm volatile("cp.async.wait_group 1;");   // tile t done
        } else {
            asm volatile("cp.async.wait_group 0;");
        }
        __syncthreads();

        const float* sp = (const float*)stage[t & 1];
        // Thread tid = pixel tid of this tile (group tid>>2, lane tid&3):
        // sp[s*256 + tid] is stream s's value for this pixel. Conflict-free.
        const float g0 = sp[0 * 256 + tid];
        const float r0 = sp[10 * 256 + tid];

        {   // focal (branchless, single log)
            const bool  pos  = (g0 >= 0.1f);            // FOCAL_THR
            const bool  m0   = (g0 >= 0.0f);
            const float safe = fminf(fmaxf(r0, 1e-6f), 1.0f - 1e-6f);
            const float larg = pos ? (safe + EPSF) : (1.0f + EPSF - safe);
            const float lg   = __logf(larg);            // larg > 0 always
            const float d0   = g0 - r0;
            const float om   = 1.0f - g0;
            const float om2  = om * om;
            float w = pos ? (d0 * d0) : (r0 * r0 * (om2 * om2));
            if (!m0) w = 0.0f;
            a_f -= w * lg;
            if (pos) a_np += 1.0f;
        }

        if (g0 == 1.0f) {                               // mv-masked terms
            a_nv += 1.0f;
            const float g1 = sp[1*256+tid], r1 = sp[11*256+tid];
            const float g2 = sp[2*256+tid], r2 = sp[12*256+tid];
            const float g3 = sp[3*256+tid], r3 = sp[13*256+tid];
            const float g4 = sp[4*256+tid], r4 = sp[14*256+tid];
            const float g5 = sp[5*256+tid], r5 = sp[15*256+tid];
            const float g6 = sp[6*256+tid], r6 = sp[16*256+tid];
            const float g7 = sp[7*256+tid], r7 = sp[17*256+tid];
            const float g8 = sp[8*256+tid], r8 = sp[18*256+tid];
            const float g9 = sp[9*256+tid], r9 = sp[19*256+tid];

            // pos (0.5 = POS_W/2) + height (0.1 = LEN_W)
            a_A += 0.5f * (sl1(r1 - g1) + sl1(r2 - g2)) + 0.1f * sl1(r9 - g9);
            // length straight/crossed (0.05 = LEN_W/2)
            a_B += 0.05f * (sl1(r3 - g3) + sl1(r6 - g6));
            a_C += 0.05f * (sl1(r3 - g6) + sl1(r6 - g3));
            // trig (0.5 = TRIG_W/2)
            const float d44 = r4 - g4, d77 = r7 - g7;
            const float d55 = r5 - g5, d88 = r8 - g8;
            a_B += 0.5f * (d44*d44 + d77*d77 + d55*d55 + d88*d88);
            const float d47 = r4 - g7, d74 = r7 - g4;
            const float d58 = r5 - g8, d85 = r8 - g5;
            a_C += 0.5f * (d47*d47 + d74*d74 + d58*d58 + d85*d85);
            // const (0.5 = CONST_W)
            const float c1 = 1.0f - r5*r5 - r4*r4;
            const float c2 = 1.0f - r8*r8 - r7*r7;
            a_A += 0.5f * (c1*c1 + c2*c2);
        }
        __syncthreads();   // all reads of this stage done before its reuse
    }

    // Block reduction: warp shuffle -> shared -> per-block partial slot.
    float acc[NACC] = {a_nv, a_np, a_f, a_A, a_B, a_C};
    __shared__ float sh[BLK/32][NACC];
    const int lane = tid & 31;
    const int warp = tid >> 5;
#pragma unroll
    for (int k = 0; k < NACC; k++) {
        float v = acc[k];
#pragma unroll
        for (int o = 16; o > 0; o >>= 1)
            v += __shfl_down_sync(0xffffffffu, v, o);
        if (lane == 0) sh[warp][k] = v;
    }
    __syncthreads();
    if (tid < NACC) {
        float v = 0.0f;
#pragma unroll
        for (int w = 0; w < BLK/32; w++) v += sh[w][tid];
        g_part[tid][blockIdx.x] = v;
    }

    // Last-block-done: the final block to arrive reduces all partials.
    __shared__ bool is_last;
    __threadfence();
    __syncthreads();
    if (tid == 0) {
        unsigned int old = atomicAdd(&g_count, 1u);
        is_last = (old == GRID - 1);
    }
    __syncthreads();
    if (!is_last) return;

    __threadfence();   // ensure we see every block's partials

    // 6 warps reduce the 6 accumulators over all 1920 block partials.
    __shared__ float tot[NACC];
    if (warp < NACC) {
        float v = 0.0f;
        for (int j = lane; j < GRID; j += 32) v += g_part[warp][j];
#pragma unroll
        for (int o = 16; o > 0; o >>= 1)
            v += __shfl_down_sync(0xffffffffu, v, o);
        if (lane == 0) tot[warp] = v;
    }
    __syncthreads();

    if (tid == 0) {
        g_count = 0;   // reset for next graph replay

        const float nv      = tot[0];
        const float num_pos = tot[1];
        const float S       = tot[2];
        const float focal = (num_pos == 0.0f) ? S : S / num_pos;
        out[0] = focal + (tot[3] + fminf(tot[4], tot[5])) / nv;
    }
}

extern "C" void kernel_launch(void* const* d_in, const int* in_sizes, int n_in,
                              void* d_out, int out_size) {
    const float* re = (const float*)d_in[0];
    const float* gt = (const float*)d_in[1];
    float* out = (float*)d_out;

    loss_kernel<<<GRID, BLK>>>(re, gt, out);
}